// round 2
// baseline (speedup 1.0000x reference)
#include <cuda_runtime.h>
#include <math.h>

// ---------------- problem constants ----------------
#define BB 4
#define NN 4096
#define DD 1024
#define HH 16
#define HD 64
#define MTOT (BB*NN)          // 16384
#define N3D (3*DD)            // 3072
#define NSCALES 11

// D4 taps: y[n] = sum_t D4[t] * field[n - (3-t)*d]
#define C0 0.4829629131445341f   // shift 3d
#define C1 0.8365163037378079f   // shift 2d
#define C2 0.2241438680420134f   // shift d
#define C3 (-0.1294095225512604f) // shift 0

// ---------------- scratch (device globals; allocation-free) ----------------
__device__ float g_qkv   [(size_t)MTOT * N3D];      // 192 MB
__device__ float g_gate  [(size_t)MTOT * DD];       // 64 MB
__device__ float g_field [(size_t)BB*HH*HD*NN];     // [bh][d][n] 64 MB
__device__ float g_acc   [(size_t)BB*HH*HD*NN];     // 64 MB
__device__ float g_field3[(size_t)BB*HH*HD*NN];     // 64 MB
__device__ float g_pre   [(size_t)MTOT * DD];       // 64 MB
__device__ float g_gains [NSCALES*HH];
__device__ float g_sw    [2];
__device__ float g_coup  [HH*HH];

// ---------------- K0: tiny prep (softmaxes, sigmoids) ----------------
__global__ void prep_kernel(const float* __restrict__ scale_gain,
                            const float* __restrict__ skip_w,
                            const float* __restrict__ coupling) {
    int t = threadIdx.x;
    if (t < HH) {
        // gains: softmax over scales (axis 0) for head column t
        float m = -1e30f;
        for (int j = 0; j < NSCALES; j++) m = fmaxf(m, scale_gain[j*HH + t]);
        float e[NSCALES]; float s = 0.f;
        for (int j = 0; j < NSCALES; j++) { e[j] = expf(scale_gain[j*HH + t] - m); s += e[j]; }
        for (int j = 0; j < NSCALES; j++) g_gains[j*HH + t] = e[j] / s;
        // coupling: softmax over row t
        float m2 = -1e30f;
        for (int j = 0; j < HH; j++) m2 = fmaxf(m2, coupling[t*HH + j]);
        float e2[HH]; float s2 = 0.f;
        for (int j = 0; j < HH; j++) { e2[j] = expf(coupling[t*HH + j] - m2); s2 += e2[j]; }
        for (int j = 0; j < HH; j++) g_coup[t*HH + j] = e2[j] / s2;
    }
    if (t < 2) g_sw[t] = 1.f / (1.f + expf(-skip_w[t]));
}

// ---------------- SGEMM: C[M,N] = A[M,K]@B[K,N] + bias ; ACT=1 -> sigmoid ----
// BM=BN=128, BK=8, 256 threads, 8x8 per-thread tile. All dims divide tiles.
template<int ACT>
__global__ __launch_bounds__(256)
void sgemm_kernel(const float* __restrict__ A, int lda,
                  const float* __restrict__ B, int ldb,
                  const float* __restrict__ bias,
                  float* __restrict__ C, int ldc, int K) {
    __shared__ float As[8][128];
    __shared__ float Bs[8][128];
    const int tid  = threadIdx.x;
    const int row0 = blockIdx.y * 128;
    const int col0 = blockIdx.x * 128;
    const int aRow = tid >> 1;            // 0..127
    const int aCol = (tid & 1) * 4;       // 0 or 4
    const int bRow = tid >> 5;            // 0..7
    const int bCol = (tid & 31) * 4;      // 0..124
    const int tr   = (tid >> 4) * 8;      // 0..120
    const int tc   = (tid & 15) * 8;

    float acc[8][8];
    #pragma unroll
    for (int i = 0; i < 8; i++)
        #pragma unroll
        for (int j = 0; j < 8; j++) acc[i][j] = 0.f;

    for (int k0 = 0; k0 < K; k0 += 8) {
        float4 a4 = *reinterpret_cast<const float4*>(A + (size_t)(row0 + aRow)*lda + k0 + aCol);
        As[aCol+0][aRow] = a4.x; As[aCol+1][aRow] = a4.y;
        As[aCol+2][aRow] = a4.z; As[aCol+3][aRow] = a4.w;
        float4 b4 = *reinterpret_cast<const float4*>(B + (size_t)(k0 + bRow)*ldb + col0 + bCol);
        *reinterpret_cast<float4*>(&Bs[bRow][bCol]) = b4;
        __syncthreads();
        #pragma unroll
        for (int kk = 0; kk < 8; kk++) {
            float ra[8], rb[8];
            #pragma unroll
            for (int i = 0; i < 8; i++) ra[i] = As[kk][tr + i];
            #pragma unroll
            for (int j = 0; j < 8; j++) rb[j] = Bs[kk][tc + j];
            #pragma unroll
            for (int i = 0; i < 8; i++)
                #pragma unroll
                for (int j = 0; j < 8; j++)
                    acc[i][j] += ra[i] * rb[j];
        }
        __syncthreads();
    }
    #pragma unroll
    for (int i = 0; i < 8; i++) {
        #pragma unroll
        for (int j = 0; j < 8; j++) {
            float c = acc[i][j] + bias[col0 + tc + j];
            if (ACT == 1) c = 1.f / (1.f + __expf(-c));
            C[(size_t)(row0 + tr + i)*ldc + col0 + tc + j] = c;
        }
    }
}

// ---------------- K3: field[bh][d][n] = v * ||k|| (transposed layout) -------
__global__ __launch_bounds__(256)
void field_kernel(const float* __restrict__ qkv) {
    const int bh = blockIdx.y;              // b*16 + h
    const int b  = bh >> 4, h = bh & 15;
    const int n0 = blockIdx.x * 32;
    __shared__ float s_kmag[32];
    __shared__ float s_t[64][33];
    const int tid = threadIdx.x, lane = tid & 31, warp = tid >> 5;

    // k magnitudes: each of 8 warps handles 4 n's
    #pragma unroll
    for (int i = 0; i < 4; i++) {
        int nl = warp*4 + i;
        const float* kp = qkv + ((size_t)(b*NN + n0 + nl))*N3D + DD + h*HD;
        float2 kv = reinterpret_cast<const float2*>(kp)[lane];
        float ss = kv.x*kv.x + kv.y*kv.y;
        #pragma unroll
        for (int o = 16; o; o >>= 1) ss += __shfl_xor_sync(0xffffffff, ss, o);
        if (lane == 0) s_kmag[nl] = sqrtf(ss);
    }
    __syncthreads();
    // v * kmag into smem (coalesced read)
    for (int idx = tid; idx < 2048; idx += 256) {
        int nl = idx >> 6, d = idx & 63;
        float v = qkv[((size_t)(b*NN + n0 + nl))*N3D + 2*DD + h*HD + d];
        s_t[d][nl] = v * s_kmag[nl];
    }
    __syncthreads();
    // transposed coalesced write
    for (int idx = tid; idx < 2048; idx += 256) {
        int d = idx >> 5, nl = idx & 31;
        g_field[((size_t)bh*HD + d)*NN + n0 + nl] = s_t[d][nl];
    }
}

// ---------------- K4: 11-scale pyramid + sparse skips, one (bh,d) row -------
__global__ __launch_bounds__(256)
void pyramid_kernel() {
    const int r = blockIdx.x;               // bh*64 + d
    const int h = (r >> 6) & 15;
    const float* row_g = g_field + (size_t)r * NN;
    __shared__ float s_row[NN];
    __shared__ float s_acc[NN];
    const int tid = threadIdx.x;
    for (int i = tid; i < NN/4; i += 256)
        reinterpret_cast<float4*>(s_row)[i] = reinterpret_cast<const float4*>(row_g)[i];
    float g[NSCALES];
    #pragma unroll
    for (int j = 0; j < NSCALES; j++) g[j] = g_gains[j*HH + h];
    const float sw0 = g_sw[0], sw1 = g_sw[1];
    __syncthreads();
    for (int n = tid; n < NN; n += 256) {
        float acc = 0.f;
        #pragma unroll
        for (int j = 0; j < NSCALES; j++) {
            int d = 1 << j;
            float y = C3 * s_row[n];
            if (n >= d)     y += C2 * s_row[n - d];
            if (n >= 2*d)   y += C1 * s_row[n - 2*d];
            if (n >= 3*d)   y += C0 * s_row[n - 3*d];
            acc += g[j] * y;
        }
        s_acc[n] = acc;
    }
    __syncthreads();
    float* out_g = g_acc + (size_t)r * NN;
    for (int n = tid; n < NN; n += 256) {
        float v = s_acc[n];
        if (n >= 512)  v += sw0 * s_acc[n - 512];
        if (n >= 1024) v += sw1 * s_acc[n - 1024];
        out_g[n] = v;
    }
}

// ---------------- K5: head coupling, register-resident 16x16 mix ------------
__global__ __launch_bounds__(256)
void coupling_kernel() {
    size_t idx = (size_t)blockIdx.x * 256 + threadIdx.x;  // over B*HD*NN
    int n = (int)(idx & (NN - 1));
    int d = (int)((idx >> 12) & 63);
    int b = (int)(idx >> 18);
    float in[HH];
    #pragma unroll
    for (int j = 0; j < HH; j++)
        in[j] = g_acc[(((size_t)(b*HH + j))*HD + d)*NN + n];
    #pragma unroll
    for (int i = 0; i < HH; i++) {
        float o = 0.f;
        #pragma unroll
        for (int j = 0; j < HH; j++) o += g_coup[i*HH + j] * in[j];
        g_field3[(((size_t)(b*HH + i))*HD + d)*NN + n] = o;
    }
}

// ---------------- K6: transpose back to [B,N,D] and apply gate --------------
__global__ __launch_bounds__(256)
void gather_kernel() {
    const int bh = blockIdx.y;
    const int b = bh >> 4, h = bh & 15;
    const int n0 = blockIdx.x * 32;
    __shared__ float s[64][33];
    const int tid = threadIdx.x;
    for (int idx = tid; idx < 2048; idx += 256) {
        int d = idx >> 5, nl = idx & 31;
        s[d][nl] = g_field3[((size_t)bh*HD + d)*NN + n0 + nl];
    }
    __syncthreads();
    for (int idx = tid; idx < 2048; idx += 256) {
        int nl = idx >> 6, d = idx & 63;
        size_t addr = ((size_t)(b*NN + n0 + nl))*DD + h*HD + d;
        g_pre[addr] = s[d][nl] * g_gate[addr];
    }
}

// ---------------- launch ----------------------------------------------------
extern "C" void kernel_launch(void* const* d_in, const int* in_sizes, int n_in,
                              void* d_out, int out_size) {
    const float* x          = (const float*)d_in[0];
    const float* Wqkv       = (const float*)d_in[1];
    const float* bqkv       = (const float*)d_in[2];
    const float* Wout       = (const float*)d_in[3];
    const float* bout       = (const float*)d_in[4];
    const float* Wgate      = (const float*)d_in[5];
    const float* bgate      = (const float*)d_in[6];
    const float* scale_gain = (const float*)d_in[7];
    const float* skip_w     = (const float*)d_in[8];
    const float* coupling   = (const float*)d_in[9];
    float* out = (float*)d_out;

    float *p_qkv, *p_gate, *p_pre;
    cudaGetSymbolAddress((void**)&p_qkv,  g_qkv);
    cudaGetSymbolAddress((void**)&p_gate, g_gate);
    cudaGetSymbolAddress((void**)&p_pre,  g_pre);

    prep_kernel<<<1, 32>>>(scale_gain, skip_w, coupling);

    // GEMM1: qkv = x @ Wqkv + bqkv          [16384 x 3072]
    sgemm_kernel<0><<<dim3(N3D/128, MTOT/128), 256>>>(x, DD, Wqkv, N3D, bqkv, p_qkv, N3D, DD);
    // GEMM2: gate = sigmoid(q @ Wgate + bgate)   (q = qkv[:, :1024], lda=3072)
    sgemm_kernel<1><<<dim3(DD/128, MTOT/128), 256>>>(p_qkv, N3D, Wgate, DD, bgate, p_gate, DD, DD);

    field_kernel   <<<dim3(NN/32, BB*HH), 256>>>(p_qkv);
    pyramid_kernel <<<BB*HH*HD, 256>>>();
    coupling_kernel<<<(BB*HD*NN)/256, 256>>>();
    gather_kernel  <<<dim3(NN/32, BB*HH), 256>>>();

    // GEMM3: out = pre @ Wout + bout        [16384 x 1024]
    sgemm_kernel<0><<<dim3(DD/128, MTOT/128), 256>>>(p_pre, DD, Wout, DD, bout, out, DD, DD);
}

// round 3
// speedup vs baseline: 3.2245x; 3.2245x over previous
#include <cuda_runtime.h>
#include <math.h>
#include <stdint.h>

// ---------------- problem constants ----------------
#define BB 4
#define NN 4096
#define DD 1024
#define HH 16
#define HD 64
#define MTOT (BB*NN)          // 16384
#define N3D (3*DD)            // 3072
#define NSCALES 11

#define C0 0.4829629131445341f
#define C1 0.8365163037378079f
#define C2 0.2241438680420134f
#define C3 (-0.1294095225512604f)

// ---------------- scratch (device globals; allocation-free) ----------------
__device__ float g_qkv   [(size_t)MTOT * N3D];      // 192 MB
__device__ float g_q32   [(size_t)MTOT * DD];       // 64 MB (tf32-rounded q)
__device__ float g_x32   [(size_t)MTOT * DD];       // 64 MB (tf32-rounded x)
__device__ float g_gate  [(size_t)MTOT * DD];       // 64 MB
__device__ float g_field [(size_t)BB*HH*HD*NN];     // [bh][d][n]
__device__ float g_acc   [(size_t)BB*HH*HD*NN];
__device__ float g_field3[(size_t)BB*HH*HD*NN];
__device__ float g_pre   [(size_t)MTOT * DD];       // tf32-rounded gated field
__device__ float g_wqkvT [(size_t)N3D * DD];        // 12 MB
__device__ float g_wgateT[(size_t)DD * DD];
__device__ float g_woutT [(size_t)DD * DD];
__device__ float g_gains [NSCALES*HH];
__device__ float g_sw    [2];
__device__ float g_coup  [HH*HH];

// ---------------- helpers ----------------
__device__ __forceinline__ float tf32r(float x) {
    uint32_t u;
    asm("cvt.rna.tf32.f32 %0, %1;" : "=r"(u) : "f"(x));
    return __uint_as_float(u);
}
__device__ __forceinline__ void cpa16(uint32_t s, const void* g) {
    asm volatile("cp.async.cg.shared.global [%0], [%1], 16;\n" :: "r"(s), "l"(g));
}
__device__ __forceinline__ void mma_tf32(float* d, const uint32_t* a, const uint32_t* b) {
    asm volatile(
        "mma.sync.aligned.m16n8k8.row.col.f32.tf32.tf32.f32 "
        "{%0,%1,%2,%3}, {%4,%5,%6,%7}, {%8,%9}, {%0,%1,%2,%3};\n"
        : "+f"(d[0]), "+f"(d[1]), "+f"(d[2]), "+f"(d[3])
        : "r"(a[0]), "r"(a[1]), "r"(a[2]), "r"(a[3]), "r"(b[0]), "r"(b[1]));
}

// ---------------- K0: tiny prep ----------------
__global__ void prep_kernel(const float* __restrict__ scale_gain,
                            const float* __restrict__ skip_w,
                            const float* __restrict__ coupling) {
    int t = threadIdx.x;
    if (t < HH) {
        float m = -1e30f;
        for (int j = 0; j < NSCALES; j++) m = fmaxf(m, scale_gain[j*HH + t]);
        float e[NSCALES]; float s = 0.f;
        for (int j = 0; j < NSCALES; j++) { e[j] = expf(scale_gain[j*HH + t] - m); s += e[j]; }
        for (int j = 0; j < NSCALES; j++) g_gains[j*HH + t] = e[j] / s;
        float m2 = -1e30f;
        for (int j = 0; j < HH; j++) m2 = fmaxf(m2, coupling[t*HH + j]);
        float e2[HH]; float s2 = 0.f;
        for (int j = 0; j < HH; j++) { e2[j] = expf(coupling[t*HH + j] - m2); s2 += e2[j]; }
        for (int j = 0; j < HH; j++) g_coup[t*HH + j] = e2[j] / s2;
    }
    if (t < 2) g_sw[t] = 1.f / (1.f + expf(-skip_w[t]));
}

// ---------------- weight transpose + tf32 round: Wt[n][k] = rna(W[k][n]) ----
__global__ __launch_bounds__(256)
void wtrans_kernel(const float* __restrict__ W, float* __restrict__ Wt,
                   int K, int Nw) {
    __shared__ float s[32][33];
    int n0 = blockIdx.x * 32, k0 = blockIdx.y * 32;
    int tx = threadIdx.x & 31, ty = threadIdx.x >> 5;  // ty 0..7
    #pragma unroll
    for (int i = 0; i < 32; i += 8)
        s[ty + i][tx] = W[(size_t)(k0 + ty + i) * Nw + n0 + tx];
    __syncthreads();
    #pragma unroll
    for (int i = 0; i < 32; i += 8)
        Wt[(size_t)(n0 + ty + i) * K + k0 + tx] = tf32r(s[tx][ty + i]);
}

// ---------------- round x to tf32 ----------------
__global__ __launch_bounds__(256)
void roundx_kernel(const float* __restrict__ x) {
    size_t i = (size_t)blockIdx.x * 256 + threadIdx.x;
    float4 v = reinterpret_cast<const float4*>(x)[i];
    v.x = tf32r(v.x); v.y = tf32r(v.y); v.z = tf32r(v.z); v.w = tf32r(v.w);
    reinterpret_cast<float4*>(g_x32)[i] = v;
}

// ---------------- tf32 tensor-core GEMM: C = A[M,K] @ Bt[N,K]^T + bias -----
// BM=BN=128, BK=32, 256 threads, 8 warps (2x4), warp tile 64x32.
// A and Bt must be pre-rounded to tf32 values stored as fp32.
#define SROW 36                 // smem row stride (floats); bank-conflict-free
#define ASZ (128*SROW)          // 4608 floats per operand per stage
#define STAGEF (2*ASZ)          // floats per stage (A then B)
#define GSMEM (2*STAGEF*4)      // 73728 bytes

template<int ACT, int QDUP>
__global__ __launch_bounds__(256)
void mma_gemm(const float* __restrict__ A, int lda,
              const float* __restrict__ Bt, int ldb,
              const float* __restrict__ bias,
              float* __restrict__ C, int ldc, int K) {
    extern __shared__ float smem[];
    const int tid  = threadIdx.x;
    const int lane = tid & 31;
    const int warp = tid >> 5;
    const int row0 = blockIdx.y * 128;
    const int col0 = blockIdx.x * 128;
    const int wr0  = (warp >> 2) * 64;
    const int wc0  = (warp & 3) * 32;
    const int lq   = lane >> 2;   // 0..7
    const int lr   = lane & 3;    // 0..3

    const int arow  = tid >> 3;       // 0..31
    const int acol4 = (tid & 7) * 4;  // 0..28

    const float* Ag = A  + (size_t)(row0 + arow) * lda + acol4;
    const float* Bg = Bt + (size_t)(col0 + arow) * ldb + acol4;
    const uint32_t smem_base = (uint32_t)__cvta_generic_to_shared(smem);
    const uint32_t sa0 = smem_base + ((arow * SROW + acol4) << 2);

    float acc[4][4][4];
    #pragma unroll
    for (int r = 0; r < 4; r++)
        #pragma unroll
        for (int c = 0; c < 4; c++)
            #pragma unroll
            for (int e = 0; e < 4; e++) acc[r][c][e] = 0.f;

    auto load_tile = [&](int stage, int kt) {
        const float* Agk = Ag + kt * 32;
        const float* Bgk = Bg + kt * 32;
        uint32_t sa = sa0 + stage * (STAGEF * 4);
        uint32_t sb = sa + ASZ * 4;
        #pragma unroll
        for (int i = 0; i < 4; i++) {
            cpa16(sa + i * (32 * SROW * 4), Agk + (size_t)i * 32 * lda);
            cpa16(sb + i * (32 * SROW * 4), Bgk + (size_t)i * 32 * ldb);
        }
        asm volatile("cp.async.commit_group;\n");
    };

    const int KT = K >> 5;
    load_tile(0, 0);

    for (int kt = 0; kt < KT; kt++) {
        if (kt + 1 < KT) {
            load_tile((kt + 1) & 1, kt + 1);
            asm volatile("cp.async.wait_group 1;\n");
        } else {
            asm volatile("cp.async.wait_group 0;\n");
        }
        __syncthreads();
        const float* sA = smem + (kt & 1) * STAGEF;
        const float* sB = sA + ASZ;
        #pragma unroll
        for (int kk = 0; kk < 32; kk += 8) {
            uint32_t af[4][4], bf[4][2];
            #pragma unroll
            for (int r = 0; r < 4; r++) {
                const float* p = sA + (wr0 + r*16 + lq) * SROW + kk + lr;
                af[r][0] = __float_as_uint(p[0]);
                af[r][1] = __float_as_uint(p[8*SROW]);
                af[r][2] = __float_as_uint(p[4]);
                af[r][3] = __float_as_uint(p[8*SROW + 4]);
            }
            #pragma unroll
            for (int c = 0; c < 4; c++) {
                const float* p = sB + (wc0 + c*8 + lq) * SROW + kk + lr;
                bf[c][0] = __float_as_uint(p[0]);
                bf[c][1] = __float_as_uint(p[4]);
            }
            #pragma unroll
            for (int r = 0; r < 4; r++)
                #pragma unroll
                for (int c = 0; c < 4; c++)
                    mma_tf32(acc[r][c], af[r], bf[c]);
        }
        __syncthreads();
    }

    // epilogue
    #pragma unroll
    for (int r = 0; r < 4; r++) {
        int row = row0 + wr0 + r*16 + lq;
        #pragma unroll
        for (int c = 0; c < 4; c++) {
            int col = col0 + wc0 + c*8 + lr*2;
            float2 b2 = *reinterpret_cast<const float2*>(bias + col);
            float v0 = acc[r][c][0] + b2.x, v1 = acc[r][c][1] + b2.y;
            float v2 = acc[r][c][2] + b2.x, v3 = acc[r][c][3] + b2.y;
            if (ACT) {
                v0 = 1.f/(1.f + __expf(-v0)); v1 = 1.f/(1.f + __expf(-v1));
                v2 = 1.f/(1.f + __expf(-v2)); v3 = 1.f/(1.f + __expf(-v3));
            }
            *reinterpret_cast<float2*>(C + (size_t)row*ldc + col)     = make_float2(v0, v1);
            *reinterpret_cast<float2*>(C + (size_t)(row+8)*ldc + col) = make_float2(v2, v3);
            if (QDUP && col < DD) {
                *reinterpret_cast<float2*>(g_q32 + (size_t)row*DD + col) =
                    make_float2(tf32r(v0), tf32r(v1));
                *reinterpret_cast<float2*>(g_q32 + (size_t)(row+8)*DD + col) =
                    make_float2(tf32r(v2), tf32r(v3));
            }
        }
    }
}

// ---------------- field[bh][d][n] = v * ||k|| -------------------------------
__global__ __launch_bounds__(256)
void field_kernel(const float* __restrict__ qkv) {
    const int bh = blockIdx.y;
    const int b  = bh >> 4, h = bh & 15;
    const int n0 = blockIdx.x * 32;
    __shared__ float s_kmag[32];
    __shared__ float s_t[64][33];
    const int tid = threadIdx.x, lane = tid & 31, warp = tid >> 5;
    #pragma unroll
    for (int i = 0; i < 4; i++) {
        int nl = warp*4 + i;
        const float* kp = qkv + ((size_t)(b*NN + n0 + nl))*N3D + DD + h*HD;
        float2 kv = reinterpret_cast<const float2*>(kp)[lane];
        float ss = kv.x*kv.x + kv.y*kv.y;
        #pragma unroll
        for (int o = 16; o; o >>= 1) ss += __shfl_xor_sync(0xffffffff, ss, o);
        if (lane == 0) s_kmag[nl] = sqrtf(ss);
    }
    __syncthreads();
    for (int idx = tid; idx < 2048; idx += 256) {
        int nl = idx >> 6, d = idx & 63;
        float v = qkv[((size_t)(b*NN + n0 + nl))*N3D + 2*DD + h*HD + d];
        s_t[d][nl] = v * s_kmag[nl];
    }
    __syncthreads();
    for (int idx = tid; idx < 2048; idx += 256) {
        int d = idx >> 5, nl = idx & 31;
        g_field[((size_t)bh*HD + d)*NN + n0 + nl] = s_t[d][nl];
    }
}

// ---------------- pyramid + sparse skips ------------------------------------
__global__ __launch_bounds__(256)
void pyramid_kernel() {
    const int r = blockIdx.x;
    const int h = (r >> 6) & 15;
    const float* row_g = g_field + (size_t)r * NN;
    __shared__ float s_row[NN];
    __shared__ float s_acc[NN];
    const int tid = threadIdx.x;
    for (int i = tid; i < NN/4; i += 256)
        reinterpret_cast<float4*>(s_row)[i] = reinterpret_cast<const float4*>(row_g)[i];
    float g[NSCALES];
    #pragma unroll
    for (int j = 0; j < NSCALES; j++) g[j] = g_gains[j*HH + h];
    const float sw0 = g_sw[0], sw1 = g_sw[1];
    __syncthreads();
    for (int n = tid; n < NN; n += 256) {
        float acc = 0.f;
        #pragma unroll
        for (int j = 0; j < NSCALES; j++) {
            int d = 1 << j;
            float y = C3 * s_row[n];
            if (n >= d)     y += C2 * s_row[n - d];
            if (n >= 2*d)   y += C1 * s_row[n - 2*d];
            if (n >= 3*d)   y += C0 * s_row[n - 3*d];
            acc += g[j] * y;
        }
        s_acc[n] = acc;
    }
    __syncthreads();
    float* out_g = g_acc + (size_t)r * NN;
    for (int n = tid; n < NN; n += 256) {
        float v = s_acc[n];
        if (n >= 512)  v += sw0 * s_acc[n - 512];
        if (n >= 1024) v += sw1 * s_acc[n - 1024];
        out_g[n] = v;
    }
}

// ---------------- head coupling ---------------------------------------------
__global__ __launch_bounds__(256)
void coupling_kernel() {
    size_t idx = (size_t)blockIdx.x * 256 + threadIdx.x;  // over B*HD*NN
    int n = (int)(idx & (NN - 1));
    int d = (int)((idx >> 12) & 63);
    int b = (int)(idx >> 18);
    float in[HH];
    #pragma unroll
    for (int j = 0; j < HH; j++)
        in[j] = g_acc[(((size_t)(b*HH + j))*HD + d)*NN + n];
    #pragma unroll
    for (int i = 0; i < HH; i++) {
        float o = 0.f;
        #pragma unroll
        for (int j = 0; j < HH; j++) o += g_coup[i*HH + j] * in[j];
        g_field3[(((size_t)(b*HH + i))*HD + d)*NN + n] = o;
    }
}

// ---------------- transpose back + gate + tf32 round ------------------------
__global__ __launch_bounds__(256)
void gather_kernel() {
    const int bh = blockIdx.y;
    const int b = bh >> 4, h = bh & 15;
    const int n0 = blockIdx.x * 32;
    __shared__ float s[64][33];
    const int tid = threadIdx.x;
    for (int idx = tid; idx < 2048; idx += 256) {
        int d = idx >> 5, nl = idx & 31;
        s[d][nl] = g_field3[((size_t)bh*HD + d)*NN + n0 + nl];
    }
    __syncthreads();
    for (int idx = tid; idx < 2048; idx += 256) {
        int nl = idx >> 6, d = idx & 63;
        size_t addr = ((size_t)(b*NN + n0 + nl))*DD + h*HD + d;
        g_pre[addr] = tf32r(s[d][nl] * g_gate[addr]);
    }
}

// ---------------- launch ----------------------------------------------------
extern "C" void kernel_launch(void* const* d_in, const int* in_sizes, int n_in,
                              void* d_out, int out_size) {
    const float* x          = (const float*)d_in[0];
    const float* Wqkv       = (const float*)d_in[1];
    const float* bqkv       = (const float*)d_in[2];
    const float* Wout       = (const float*)d_in[3];
    const float* bout       = (const float*)d_in[4];
    const float* Wgate      = (const float*)d_in[5];
    const float* bgate      = (const float*)d_in[6];
    const float* scale_gain = (const float*)d_in[7];
    const float* skip_w     = (const float*)d_in[8];
    const float* coupling   = (const float*)d_in[9];
    float* out = (float*)d_out;

    float *p_qkv, *p_gate, *p_pre, *p_x32, *p_q32, *p_wqkvT, *p_wgateT, *p_woutT;
    cudaGetSymbolAddress((void**)&p_qkv,    g_qkv);
    cudaGetSymbolAddress((void**)&p_gate,   g_gate);
    cudaGetSymbolAddress((void**)&p_pre,    g_pre);
    cudaGetSymbolAddress((void**)&p_x32,    g_x32);
    cudaGetSymbolAddress((void**)&p_q32,    g_q32);
    cudaGetSymbolAddress((void**)&p_wqkvT,  g_wqkvT);
    cudaGetSymbolAddress((void**)&p_wgateT, g_wgateT);
    cudaGetSymbolAddress((void**)&p_woutT,  g_woutT);

    cudaFuncSetAttribute(mma_gemm<0,1>, cudaFuncAttributeMaxDynamicSharedMemorySize, GSMEM);
    cudaFuncSetAttribute(mma_gemm<1,0>, cudaFuncAttributeMaxDynamicSharedMemorySize, GSMEM);
    cudaFuncSetAttribute(mma_gemm<0,0>, cudaFuncAttributeMaxDynamicSharedMemorySize, GSMEM);

    prep_kernel<<<1, 32>>>(scale_gain, skip_w, coupling);

    // one-time weight transposes (+ tf32 rounding) and x rounding
    wtrans_kernel<<<dim3(N3D/32, DD/32), 256>>>(Wqkv,  p_wqkvT,  DD, N3D);
    wtrans_kernel<<<dim3(DD/32,  DD/32), 256>>>(Wgate, p_wgateT, DD, DD);
    wtrans_kernel<<<dim3(DD/32,  DD/32), 256>>>(Wout,  p_woutT,  DD, DD);
    roundx_kernel<<<(MTOT*DD/4)/256, 256>>>(x);

    // GEMM1: qkv = x @ Wqkv + bqkv   (also stores tf32-rounded q)
    mma_gemm<0,1><<<dim3(N3D/128, MTOT/128), 256, GSMEM>>>(
        p_x32, DD, p_wqkvT, DD, bqkv, p_qkv, N3D, DD);
    // GEMM2: gate = sigmoid(q @ Wgate + bgate)
    mma_gemm<1,0><<<dim3(DD/128, MTOT/128), 256, GSMEM>>>(
        p_q32, DD, p_wgateT, DD, bgate, p_gate, DD, DD);

    field_kernel   <<<dim3(NN/32, BB*HH), 256>>>(p_qkv);
    pyramid_kernel <<<BB*HH*HD, 256>>>();
    coupling_kernel<<<(BB*HD*NN)/256, 256>>>();
    gather_kernel  <<<dim3(NN/32, BB*HH), 256>>>();

    // GEMM3: out = pre @ Wout + bout
    mma_gemm<0,0><<<dim3(DD/128, MTOT/128), 256, GSMEM>>>(
        p_pre, DD, p_woutT, DD, bout, out, DD, DD);
}